// round 16
// baseline (speedup 1.0000x reference)
#include <cuda_runtime.h>
#include <cstdint>

#define BATCH 4
#define C_IN 32
#define C_OUT 32
#define NNODE 163842
#define K7 7

#define TM 128                           // nodes per CTA
#define THREADS 128                      // 4 warps
#define NT2 ((NNODE + TM - 1) / TM)      // 1281

// ---- global scratch ----
__device__ float g_xt[(size_t)BATCH * NNODE * C_IN];   // x transposed [B,N,32]
// W bf16 fragment images: [j][ks2*4+nb][lane] x {hi01, hi23, lo01, lo23}
__device__ float g_wimg[K7 * 8 * 32 * 4];              // 7168 floats = 28KB
__constant__ float cB[C_OUT];

// ---------------------------------------------------------------------------
// helpers
// ---------------------------------------------------------------------------
// bf16 hi/lo pack of a value pair: hi = top-16-bit truncation (exact fp32),
// lo = (x - hi) truncated to bf16. Result regs are bf16x2 {x, y}.
__device__ __forceinline__ void pack_pair(float x, float y,
                                          uint32_t& hi, uint32_t& lo) {
    const uint32_t bx = __float_as_uint(x), by = __float_as_uint(y);
    hi = __byte_perm(bx, by, 0x7632);
    const float lx = x - __uint_as_float(bx & 0xFFFF0000u);
    const float ly = y - __uint_as_float(by & 0xFFFF0000u);
    lo = __byte_perm(__float_as_uint(lx), __float_as_uint(ly), 0x7632);
}

__device__ __forceinline__ void mma_bf16(float* d, const uint32_t* a,
                                         uint32_t b0, uint32_t b1) {
    asm volatile(
        "mma.sync.aligned.m16n8k16.row.col.f32.bf16.bf16.f32 "
        "{%0,%1,%2,%3}, {%4,%5,%6,%7}, {%8,%9}, {%0,%1,%2,%3};"
        : "+f"(d[0]), "+f"(d[1]), "+f"(d[2]), "+f"(d[3])
        : "r"(a[0]), "r"(a[1]), "r"(a[2]), "r"(a[3]), "r"(b0), "r"(b1));
}

// ---------------------------------------------------------------------------
// Kernel 1: transpose x [B, C_IN, N] -> xt [B, N, C_IN]; block (0,0) also
// builds the bf16 W fragment images.
// ---------------------------------------------------------------------------
__global__ __launch_bounds__(256) void transpose_kernel(const float* __restrict__ x,
                                                        const float* __restrict__ W,
                                                        float* __restrict__ xt,
                                                        float* __restrict__ wimg) {
    __shared__ float2 t2[32][65];          // pitch 65 (odd) float2
    const int b  = blockIdx.y;
    const int n0 = blockIdx.x * 128;
    const int tid = threadIdx.x;

#pragma unroll
    for (int k = 0; k < 4; k++) {
#pragma unroll
        for (int h = 0; h < 2; h++) {
            const int c  = (tid >> 5) + 8 * k;
            const int c2 = (tid & 31) + 32 * h;
            const int n  = n0 + 2 * c2;
            const float* xr = x + ((size_t)b * C_IN + c) * NNODE;
            float2 v = make_float2(0.f, 0.f);
            if (n + 1 < NNODE)      v = *(const float2*)(xr + n);
            else if (n < NNODE)     v.x = xr[n];
            t2[c][c2] = v;
        }
    }
    __syncthreads();

    const float* tf = (const float*)t2;    // pitch 130 floats
#pragma unroll
    for (int pass = 0; pass < 4; pass++) {
        const int nn = (tid >> 3) + 32 * pass;
        const int n  = n0 + nn;
        if (n < NNODE) {
            const int cb = 4 * (tid & 7);
            float4 o;
            o.x = tf[(cb + 0) * 130 + nn];
            o.y = tf[(cb + 1) * 130 + nn];
            o.z = tf[(cb + 2) * 130 + nn];
            o.w = tf[(cb + 3) * 130 + nn];
            *(float4*)(xt + ((size_t)b * NNODE + n) * C_IN + cb) = o;
        }
    }

    // Merged wsplit: bf16 hi/lo fragment images (uint16 slot per element).
    if (blockIdx.x == 0 && blockIdx.y == 0) {
        uint16_t* w16 = (uint16_t*)wimg;
        for (int i = tid; i < 32 * 224; i += 256) {
            const int o = i / 224, k = i % 224;
            const int j = k / 32, kk = k % 32;
            const int ks2 = kk >> 4, kloc = kk & 15;
            const int nb = o >> 3, n = o & 7;
            const int lane = n * 4 + ((kloc & 7) >> 1);
            const int pr   = kloc >> 3;        // reg pair 0/1
            const int half = kloc & 1;         // low/high bf16 in reg
            const float v = W[i];
            const uint32_t bits = __float_as_uint(v);
            const uint16_t h16 = (uint16_t)(bits >> 16);
            const float lof = v - __uint_as_float(bits & 0xFFFF0000u);
            const uint16_t l16 = (uint16_t)(__float_as_uint(lof) >> 16);
            const int wordbase = ((j * 8 + ks2 * 4 + nb) * 32 + lane) * 4;
            w16[(wordbase + pr) * 2 + half]     = h16;   // hi words 0,1
            w16[(wordbase + 2 + pr) * 2 + half] = l16;   // lo words 2,3
        }
    }
}

// ---------------------------------------------------------------------------
// Kernel 2: mma.sync bf16 conv (m16n8k16), 3-term hi/lo in registers.
// A fragments loaded DIRECTLY from gmem (LDG.64, L2-resident xt rows) —
// no smem A buffer, no barriers in the main loop. Each warp statically owns
// its 32 rows; per-quad row indices come from a broadcast sidx LDS.
// 6 CTAs/SM (reg-capped at 85), 24 warps for latency hiding.
// ---------------------------------------------------------------------------
__global__ __launch_bounds__(THREADS, 6) void onering_conv_mma_kernel(
    const float* __restrict__ xt,
    const int* __restrict__ neigh,
    const float* __restrict__ wimg,
    float* __restrict__ out) {

    __shared__ int sidx[TM * K7];

    const int tid  = threadIdx.x;
    const int wid  = tid >> 5;
    const int lane = tid & 31;
    const int b    = blockIdx.y;
    const int n0   = blockIdx.x * TM;

#pragma unroll
    for (int i = tid; i < TM * K7; i += THREADS) {
        const int gg = n0 * K7 + i;
        sidx[i] = (gg < NNODE * K7) ? neigh[gg] : 0;
    }
    __syncthreads();           // only barrier in the kernel

    const float* xb = xt + (size_t)b * NNODE * C_IN;

    float d[2][4][4];
#pragma unroll
    for (int mb = 0; mb < 2; mb++)
#pragma unroll
        for (int nb = 0; nb < 4; nb++)
#pragma unroll
            for (int q = 0; q < 4; q++) d[mb][nb][q] = 0.0f;

    const int g  = lane >> 2;          // fragment row within 8
    const int c2 = (lane & 3) * 2;     // fragment k base within 8
    const float4* wbase4 = (const float4*)wimg + lane;

#pragma unroll 1
    for (int j = 0; j < K7; j++) {
        const float4* wj = wbase4 + (size_t)j * 256;

        // Row pointers for this chunk (broadcast LDS: quad-uniform index).
        const float* p[2][2];          // [mb][0: row g, 1: row g+8]
#pragma unroll
        for (int mb = 0; mb < 2; mb++) {
            const int r0 = wid * 32 + mb * 16 + g;
            p[mb][0] = xb + (size_t)sidx[r0 * K7 + j] * C_IN;
            p[mb][1] = xb + (size_t)sidx[(r0 + 8) * K7 + j] * C_IN;
        }

#pragma unroll
        for (int ks = 0; ks < 2; ks++) {
            uint32_t ah[2][4], al[2][4];
#pragma unroll
            for (int mb = 0; mb < 2; mb++) {
                const int ko = ks * 16 + c2;
                const float2 v0 = *(const float2*)(p[mb][0] + ko);
                const float2 v1 = *(const float2*)(p[mb][1] + ko);
                const float2 v2 = *(const float2*)(p[mb][0] + ko + 8);
                const float2 v3 = *(const float2*)(p[mb][1] + ko + 8);
                pack_pair(v0.x, v0.y, ah[mb][0], al[mb][0]);
                pack_pair(v1.x, v1.y, ah[mb][1], al[mb][1]);
                pack_pair(v2.x, v2.y, ah[mb][2], al[mb][2]);
                pack_pair(v3.x, v3.y, ah[mb][3], al[mb][3]);
            }
#pragma unroll
            for (int nb = 0; nb < 4; nb++) {
                const float4 wv = __ldg(wj + (ks * 4 + nb) * 32);
                const uint32_t w0 = __float_as_uint(wv.x);
                const uint32_t w1 = __float_as_uint(wv.y);
                const uint32_t w2 = __float_as_uint(wv.z);
                const uint32_t w3 = __float_as_uint(wv.w);
#pragma unroll
                for (int mb = 0; mb < 2; mb++) {
                    mma_bf16(d[mb][nb], ah[mb], w0, w1);
                    mma_bf16(d[mb][nb], al[mb], w0, w1);
                    mma_bf16(d[mb][nb], ah[mb], w2, w3);
                }
            }
        }
    }

    // Epilogue (m16n8 D layout).
    const int r_lo = lane >> 2;
    const int c0   = 2 * (lane & 3);
#pragma unroll
    for (int mb = 0; mb < 2; mb++) {
        const int nrow = n0 + wid * 32 + mb * 16;
#pragma unroll
        for (int nb = 0; nb < 4; nb++) {
            const int o = nb * 8 + c0;
#pragma unroll
            for (int half = 0; half < 2; half++) {
                const int n = nrow + r_lo + half * 8;
                if (n < NNODE) {
                    float* ob = out + (size_t)b * C_OUT * NNODE + n;
                    ob[(size_t)o * NNODE]       = d[mb][nb][half * 2]     + cB[o];
                    ob[(size_t)(o + 1) * NNODE] = d[mb][nb][half * 2 + 1] + cB[o + 1];
                }
            }
        }
    }
}

// ---------------------------------------------------------------------------
// Launch
// ---------------------------------------------------------------------------
extern "C" void kernel_launch(void* const* d_in, const int* in_sizes, int n_in,
                              void* d_out, int out_size) {
    const float* x     = (const float*)d_in[0];
    const float* W     = (const float*)d_in[1];
    const float* bias  = (const float*)d_in[2];
    const int*   neigh = (const int*)d_in[3];
    float* out = (float*)d_out;

    float* xt = nullptr;
    cudaGetSymbolAddress((void**)&xt, g_xt);
    float* wimg = nullptr;
    cudaGetSymbolAddress((void**)&wimg, g_wimg);

    {
        dim3 grid((NNODE + 127) / 128, BATCH);
        transpose_kernel<<<grid, 256>>>(x, W, xt, wimg);
    }
    cudaMemcpyToSymbolAsync(cB, bias, C_OUT * sizeof(float), 0,
                            cudaMemcpyDeviceToDevice, 0);
    {
        dim3 grid(NT2, BATCH);
        onering_conv_mma_kernel<<<grid, THREADS>>>(xt, neigh, wimg, out);
    }
}